// round 13
// baseline (speedup 1.0000x reference)
#include <cuda_runtime.h>

#define NQ      22
#define NSTATE  (1u << NQ)
#define NLAYERS 8

typedef unsigned long long u64;

// SINGLE statevector buffer (33.5 MB — fully L2-resident), updated in place.
// Physical layout at layer l: logical amp t lives at phys gray^{l-1}(t).
__device__ float2 g_state[NSTATE];
// Fused single-qubit unitaries U = RX*RZ*RY (float2, for layer-0 tables)
__device__ float2 g_U[NLAYERS][NQ][4];
// ZYZ real-rotation coefficients per gate: [0]=dup(c) [1]=dup(s) [2]=dup(-s)
__device__ u64 g_Rpk[NLAYERS][NQ][3];
// Broadcast copy in constant memory (filled by D2D memcpy after prep_gates)
__constant__ u64 c_Rpk[NLAYERS][NQ][3];
// ZYZ half-angles: U = diag(e^{-ipA},e^{ipA}) * R(c,s) * diag(e^{-ipB},e^{ipB})
__device__ float g_pA[NLAYERS][NQ];
__device__ float g_pB[NLAYERS][NQ];
// Combined inter-layer diagonal tables (indexed by LOGICAL target t):
//   W_L[t] = B_L[t] * A_{L-1}[gray(t)]      (A term absent for L=1)
__device__ float2 g_Whi[NLAYERS][2048];
__device__ float2 g_Wlo[NLAYERS][2][2048];
// Product-state tables for layer 0
__device__ float2 g_Phi[2048];
__device__ float2 g_Plo[2048];

// ---------------------------------------------------------------------------
// f32x2 packed helpers
// ---------------------------------------------------------------------------
__device__ __forceinline__ u64 pk2(float lo, float hi) {
    u64 r; asm("mov.b64 %0, {%1, %2};" : "=l"(r) : "f"(lo), "f"(hi)); return r;
}
__device__ __forceinline__ void unpk2(u64 v, float& lo, float& hi) {
    asm("mov.b64 {%0, %1}, %2;" : "=f"(lo), "=f"(hi) : "l"(v));
}
__device__ __forceinline__ u64 f2mul(u64 a, u64 b) {
    u64 r; asm("mul.rn.f32x2 %0, %1, %2;" : "=l"(r) : "l"(a), "l"(b)); return r;
}
__device__ __forceinline__ u64 f2fma(u64 a, u64 b, u64 c) {
    u64 r; asm("fma.rn.f32x2 %0, %1, %2, %3;" : "=l"(r) : "l"(a), "l"(b), "l"(c)); return r;
}
__device__ __forceinline__ float2 cmulf(float2 a, float2 b) {
    return make_float2(a.x * b.x - a.y * b.y, a.x * b.y + a.y * b.x);
}
__device__ __forceinline__ u64 apply_phase(float2 w, u64 x) {
    float re, im; unpk2(x, re, im);
    return pk2(w.x * re - w.y * im, w.x * im + w.y * re);
}

// gray^e(t), e in [0,6]: gray = t^(t>>1); gray^(2^k) = t^(t>>2^k); factors commute.
__device__ __forceinline__ unsigned gpow(unsigned t, int e) {
    if (e & 1) t ^= t >> 1;
    if (e & 2) t ^= t >> 2;
    if (e & 4) t ^= t >> 4;
    return t;
}

// Real Givens butterfly: y0 = c*x0 - s*x1 ; y1 = s*x0 + c*x1  (4 f32x2 ops)
__device__ __forceinline__ void rbfly(u64 c, u64 s, u64 ns, u64& x0, u64& x1) {
    u64 y0 = f2fma(c, x0, f2mul(ns, x1));
    u64 y1 = f2fma(c, x1, f2mul(s, x0));
    x0 = y0; x1 = y1;
}

// Apply gate (layer, q) across register bit K; coefs from constant memory.
template<int K>
__device__ __forceinline__ void gate_q(int layer, int q, u64 a[16]) {
    u64 c = c_Rpk[layer][q][0], s = c_Rpk[layer][q][1], ns = c_Rpk[layer][q][2];
#pragma unroll
    for (int m = 0; m < 8; m++) {
        int j0 = ((m >> K) << (K + 1)) | (m & ((1 << K) - 1));
        rbfly(c, s, ns, a[j0], a[j0 | (1 << K)]);
    }
}

// Swizzles (verified conflict-free / half-warp-only for each kernel's patterns)
__device__ __forceinline__ int SWL(int i) { return i ^ ((i >> 4) & 15); }   // kernelL
__device__ __forceinline__ int SWH(int i) { return i ^ ((i >> 2) & 24); }   // kernelH

// ---------------------------------------------------------------------------
// Prep stage 1 (1 block): fused U matrices + ZYZ decomposition per gate.
// ---------------------------------------------------------------------------
__global__ void prep_gates(const float* __restrict__ p) {
    int tid = threadIdx.x;
    if (tid >= NLAYERS * NQ) return;
    int l = tid / NQ, q = tid % NQ;
    float ty = p[l * 3 * NQ + q];
    float tz = p[l * 3 * NQ + NQ + q];
    float tx = p[l * 3 * NQ + 2 * NQ + q];
    float cy = cosf(0.5f * ty), sy = sinf(0.5f * ty);
    float cz = cosf(0.5f * tz), sz = sinf(0.5f * tz);
    float cx = cosf(0.5f * tx), sx = sinf(0.5f * tx);
    float2 em = make_float2(cz, -sz);
    float2 ep = make_float2(cz, sz);
    float2 u00 = make_float2(cx * cy * em.x + sx * sy * ep.y,
                             cx * cy * em.y - sx * sy * ep.x);
    float2 u01 = make_float2(-cx * sy * em.x + sx * cy * ep.y,
                             -cx * sy * em.y - sx * cy * ep.x);
    float2 u10 = make_float2(sx * cy * em.y + cx * sy * ep.x,
                             -sx * cy * em.x + cx * sy * ep.y);
    float2 u11 = make_float2(-sx * sy * em.y + cx * cy * ep.x,
                             sx * sy * em.x + cx * cy * ep.y);
    g_U[l][q][0] = u00; g_U[l][q][1] = u01;
    g_U[l][q][2] = u10; g_U[l][q][3] = u11;
    float c = sqrtf(u00.x * u00.x + u00.y * u00.y);
    float s = sqrtf(u01.x * u01.x + u01.y * u01.y);
    float p00 = atan2f(u00.y, u00.x);
    float p01 = atan2f(u01.y, u01.x);
    const float PI = 3.14159265358979f;
    float pA = 0.5f * (-p00 - p01 + PI);
    float pB = 0.5f * (-p00 + p01 - PI);
    g_pA[l][q] = pA; g_pB[l][q] = pB;
    g_Rpk[l][q][0] = pk2(c, c);
    g_Rpk[l][q][1] = pk2(s, s);
    g_Rpk[l][q][2] = pk2(-s, -s);
}

// ---------------------------------------------------------------------------
// Prep stage 2 (grid-parallel): product tables + combined diag tables.
// ---------------------------------------------------------------------------
__global__ void prep_tables() {
    int idx = blockIdx.x * blockDim.x + threadIdx.x;
    if (idx < 2048) {
        int i = idx;
        float2 ph = make_float2(1.f, 0.f);
        float2 pl = make_float2(1.f, 0.f);
        for (int q = 0; q <= 10; q++) {
            int b = (i >> (10 - q)) & 1;
            ph = cmulf(ph, g_U[0][q][b * 2]);
        }
        for (int q = 11; q <= 21; q++) {
            int b = (i >> (21 - q)) & 1;
            pl = cmulf(pl, g_U[0][q][b * 2]);
        }
        g_Phi[i] = ph;
        g_Plo[i] = pl;
    } else if (idx < 2048 + 7 * 2048) {
        int k0 = idx - 2048;
        int L = 1 + (k0 >> 11), x = k0 & 2047;
        float ang = 0.f;
        for (int k = 0; k < 11; k++) {
            int xb = (x >> k) & 1;
            ang += (xb ? 1.f : -1.f) * g_pB[L][10 - k];
            if (L >= 2) {
                int gb = xb ^ ((k < 10) ? ((x >> (k + 1)) & 1) : 0);
                ang += (gb ? 1.f : -1.f) * g_pA[L - 1][10 - k];
            }
        }
        float sv, cv; sincosf(ang, &sv, &cv);
        g_Whi[L][x] = make_float2(cv, sv);
    } else if (idx < 2048 + 7 * 2048 + 7 * 2 * 2048) {
        int k0 = idx - (2048 + 7 * 2048);
        int L = 1 + (k0 >> 12), carry = (k0 >> 11) & 1, x = k0 & 2047;
        float ang = 0.f;
        for (int b = 0; b < 11; b++) {
            int xb = (x >> b) & 1;
            ang += (xb ? 1.f : -1.f) * g_pB[L][21 - b];
            if (L >= 2) {
                int gb = xb ^ ((b < 10) ? ((x >> (b + 1)) & 1) : carry);
                ang += (gb ? 1.f : -1.f) * g_pA[L - 1][21 - b];
            }
        }
        float sv, cv; sincosf(ang, &sv, &cv);
        g_Wlo[L][carry][x] = make_float2(cv, sv);
    }
}

#define SMEM_BYTES (8192 * 8)

// ---------------------------------------------------------------------------
// L kernel: logical tile = 8192 contiguous amps (bits 0..12), 12 real
// rotations on bits 0..11 (qubits 10..21). blockIdx = logical bits 13..21.
// IN-PLACE: both load and store address phys = gray^{layer-1}(t); the map
// includes all accumulated CNOT folds. The diag W_layer is applied at load
// (indexed by logical t). first=1 synthesizes the layer-0 product state
// (tables carry layer-0's CNOT via one gray; store at identity).
// ---------------------------------------------------------------------------
__global__ void __launch_bounds__(512, 2) kernelL(int layer, int first) {
    extern __shared__ u64 sh[];
    const int t = threadIdx.x;                 // 9 bits
    const unsigned h = blockIdx.x;             // logical bits 13..21 (9 bits)
    const int e = layer - 1;                   // accumulated gray exponent
    u64 a[16];

    const int b12 = t >> 8, t8 = t & 255;
    // ---- Phase A: i = (b12<<12)|(r<<8)|t8 ; reg bits local 8..11 -> qubit 13-k
    if (first) {
        const unsigned ghi = h ^ (h >> 1);
        const unsigned c12 = (h & 1u) << 12;
#pragma unroll
        for (int r = 0; r < 16; r++) {
            unsigned i = (b12 << 12) | (r << 8) | t8;
            unsigned glo = (i ^ (i >> 1)) ^ c12;
            float2 ph = g_Phi[(ghi << 2) | (glo >> 11)];
            float2 pl = g_Plo[glo & 2047];
            float2 v = cmulf(ph, pl);
            a[r] = pk2(v.x, v.y);
        }
    } else {
#pragma unroll
        for (int r = 0; r < 16; r++) {
            unsigned tf = (h << 13) | (b12 << 12) | (r << 8) | t8;
            float2 v = __ldg(&g_state[gpow(tf, e)]);
            a[r] = pk2(v.x, v.y);
        }
    }
    // Combined diag W at logical target t = (h<<13)|i:
    // xhi = t>>11 = (h<<2)|(b12<<1)|(r>>3); carry = t_11 = r>>3; xlo = t&2047.
    {
        const float2 whi0 = __ldg(&g_Whi[layer][(h << 2) | (b12 << 1)]);
        const float2 whi1 = __ldg(&g_Whi[layer][(h << 2) | (b12 << 1) | 1]);
#pragma unroll
        for (int r = 0; r < 16; r++) {
            int carry = r >> 3;
            int ilo = ((r & 7) << 8) | t8;
            float2 w = cmulf(carry ? whi1 : whi0, __ldg(&g_Wlo[layer][carry][ilo]));
            a[r] = apply_phase(w, a[r]);
        }
    }
    gate_q<0>(layer, 13, a);
    gate_q<1>(layer, 12, a);
    gate_q<2>(layer, 11, a);
    gate_q<3>(layer, 10, a);
#pragma unroll
    for (int r = 0; r < 16; r++) sh[SWL((b12 << 12) | (r << 8) | t8)] = a[r];
    __syncthreads();

    // ---- Phase B: i = (t<<4)|r ; reg bits local 0..3 -> qubit 21-k
#pragma unroll
    for (int r = 0; r < 16; r++) a[r] = sh[SWL((t << 4) | r)];
    gate_q<0>(layer, 21, a);
    gate_q<1>(layer, 20, a);
    gate_q<2>(layer, 19, a);
    gate_q<3>(layer, 18, a);
#pragma unroll
    for (int r = 0; r < 16; r++) sh[SWL((t << 4) | r)] = a[r];
    __syncthreads();

    // ---- Phase C: i = (hi5<<8)|(r<<4)|lo4 ; reg bits local 4..7 -> qubit 17-k
    const int hi5 = t >> 4, lo4 = t & 15;
#pragma unroll
    for (int r = 0; r < 16; r++) a[r] = sh[SWL((hi5 << 8) | (r << 4) | lo4)];
    gate_q<0>(layer, 17, a);
    gate_q<1>(layer, 16, a);
    gate_q<2>(layer, 15, a);
    gate_q<3>(layer, 14, a);

#pragma unroll
    for (int r = 0; r < 16; r++) {
        unsigned tf = (h << 13) | (hi5 << 8) | (r << 4) | lo4;
        float re, im; unpk2(a[r], re, im);
        g_state[gpow(tf, e)] = make_float2(re, im);
    }
}

// ---------------------------------------------------------------------------
// H kernel: logical tile bits {0..2} U {12..21} (8192 amps), 10 real
// rotations on logical bits 12..21 (qubits 0..9). blockIdx = bits 3..11.
// IN-PLACE at phys = gray^{layer-1}(j). Store is plain (post-diag deferred
// into next layer's W) OR folds final CNOT chain + |amp|^2 (probs != nullptr;
// A_7 dropped — phase-invariant). j(i) = ((i>>3)<<12) | (f<<3) | (i&7).
// ---------------------------------------------------------------------------
__global__ void __launch_bounds__(512, 2) kernelH(int layer,
                                                  float* __restrict__ probs) {
    extern __shared__ u64 sh[];
    const int t = threadIdx.x;                 // 9 bits
    const unsigned f = blockIdx.x;             // logical bits 3..11 (9 bits)
    const int e = layer - 1;
    u64 a[16];

    // ---- Phase A: i = (r<<9)|t ; reg bits local 9..12 = global 18..21 -> qubit 3-k
    const unsigned jt = ((unsigned)(t >> 3) << 12) | (f << 3) | (unsigned)(t & 7);
#pragma unroll
    for (int r = 0; r < 16; r++) {
        float2 v = __ldg(&g_state[gpow(jt | (r << 18), e)]);
        a[r] = pk2(v.x, v.y);
    }
    gate_q<0>(layer, 3, a);
    gate_q<1>(layer, 2, a);
    gate_q<2>(layer, 1, a);
    gate_q<3>(layer, 0, a);
#pragma unroll
    for (int r = 0; r < 16; r++) sh[SWH((r << 9) | t)] = a[r];
    __syncthreads();

    // ---- Phase B: i = (hi4<<9)|(r<<5)|lo5 ; local 5..8 = global 14..17 -> qubit 7-k
    const int hi4 = t >> 5, lo5 = t & 31;
#pragma unroll
    for (int r = 0; r < 16; r++) a[r] = sh[SWH((hi4 << 9) | (r << 5) | lo5)];
    gate_q<0>(layer, 7, a);
    gate_q<1>(layer, 6, a);
    gate_q<2>(layer, 5, a);
    gate_q<3>(layer, 4, a);
#pragma unroll
    for (int r = 0; r < 16; r++) sh[SWH((hi4 << 9) | (r << 5) | lo5)] = a[r];
    __syncthreads();

    // ---- Phase C: reg bits: r0,r1 -> local 3,4 (qubits 9,8); r2,r3 -> local 9,10
    // i = (t_c<<11)|(rf<<9)|(t_b<<5)|(rg<<3)|t_a
    const int t_a = t & 7, t_b = (t >> 3) & 15, t_c = t >> 7;
#pragma unroll
    for (int r = 0; r < 16; r++) {
        int i = (t_c << 11) | ((r >> 2) << 9) | (t_b << 5) | ((r & 3) << 3) | t_a;
        a[r] = sh[SWH(i)];
    }
    gate_q<0>(layer, 9, a);    // local 3 = global 12 -> qubit 9
    gate_q<1>(layer, 8, a);    // local 4 = global 13 -> qubit 8

    if (probs) {
        // layer 7: post-diag dropped (phase-invariant); fold final CNOT chain
#pragma unroll
        for (int r = 0; r < 16; r++) {
            int i = (t_c << 11) | ((r >> 2) << 9) | (t_b << 5) | ((r & 3) << 3) | t_a;
            unsigned j = (((unsigned)i >> 3) << 12) | (f << 3) | (unsigned)(i & 7);
            unsigned o = j;
            o ^= o >> 1; o ^= o >> 2; o ^= o >> 4; o ^= o >> 8; o ^= o >> 16;
            float re, im; unpk2(a[r], re, im);
            probs[o] = fmaf(re, re, im * im);
        }
    } else {
#pragma unroll
        for (int r = 0; r < 16; r++) {
            int i = (t_c << 11) | ((r >> 2) << 9) | (t_b << 5) | ((r & 3) << 3) | t_a;
            unsigned j = (((unsigned)i >> 3) << 12) | (f << 3) | (unsigned)(i & 7);
            float re, im; unpk2(a[r], re, im);
            g_state[gpow(j, e)] = make_float2(re, im);
        }
    }
}

// ---------------------------------------------------------------------------
extern "C" void kernel_launch(void* const* d_in, const int* in_sizes, int n_in,
                              void* d_out, int out_size) {
    (void)in_sizes; (void)n_in; (void)out_size;
    const float* params = (const float*)d_in[0];
    float* out = (float*)d_out;

    cudaFuncSetAttribute(kernelL, cudaFuncAttributeMaxDynamicSharedMemorySize, SMEM_BYTES);
    cudaFuncSetAttribute(kernelH, cudaFuncAttributeMaxDynamicSharedMemorySize, SMEM_BYTES);

    prep_gates<<<1, 192>>>(params);
    // Broadcast gate coefficients into constant memory (D2D copy, graph-legal)
    void* cdst = nullptr; void* csrc = nullptr;
    cudaGetSymbolAddress(&cdst, c_Rpk);
    cudaGetSymbolAddress(&csrc, g_Rpk);
    cudaMemcpyAsync(cdst, csrc, NLAYERS * NQ * 3 * sizeof(u64),
                    cudaMemcpyDeviceToDevice);
    prep_tables<<<88, 512>>>();

    // Single-buffer in-place pipeline: layer l addresses phys = gray^{l-1}(t).
    // Layer 0 folded into tables; all CNOT chains folded into the accumulated
    // gray map (final chain into the prob scatter); both diagonals of each
    // layer boundary folded into ONE phase multiply at L-load.
    kernelL<<<512, 512, SMEM_BYTES>>>(1, /*first*/1);
    kernelH<<<512, 512, SMEM_BYTES>>>(1, nullptr);
    for (int ll = 2; ll <= 7; ll++) {
        kernelL<<<512, 512, SMEM_BYTES>>>(ll, 0);
        kernelH<<<512, 512, SMEM_BYTES>>>(ll, (ll == 7) ? out : nullptr);
    }
}

// round 14
// speedup vs baseline: 1.0163x; 1.0163x over previous
#include <cuda_runtime.h>

#define NQ      22
#define NSTATE  (1u << NQ)
#define NLAYERS 8

typedef unsigned long long u64;

// Ping-pong statevector buffers (64 MB total)
__device__ __align__(16) float2 g_state[2][NSTATE];
// Fused single-qubit unitaries U = RX*RZ*RY (float2, for layer-0 tables)
__device__ float2 g_U[NLAYERS][NQ][4];
// ZYZ real-rotation coefficients per gate: [0]=dup(c) [1]=dup(s) [2]=dup(-s)
__device__ u64 g_Rpk[NLAYERS][NQ][3];
// Broadcast copy in constant memory (filled by D2D memcpy after prep_gates)
__constant__ u64 c_Rpk[NLAYERS][NQ][3];
// ZYZ half-angles
__device__ float g_pA[NLAYERS][NQ];
__device__ float g_pB[NLAYERS][NQ];
// Combined inter-layer diagonal tables, applied at L-load of layer L:
//   W_L[t] = B_L[t] * A_{L-1}[gray(t)]      (A term absent for L=1)
__device__ float2 g_Whi[NLAYERS][2048];
__device__ __align__(16) float2 g_Wlo[NLAYERS][2][2048];
// Product-state tables for layer 0
__device__ float2 g_Phi[2048];
__device__ float2 g_Plo[2048];

// ---------------------------------------------------------------------------
// f32x2 packed helpers
// ---------------------------------------------------------------------------
__device__ __forceinline__ u64 pk2(float lo, float hi) {
    u64 r; asm("mov.b64 %0, {%1, %2};" : "=l"(r) : "f"(lo), "f"(hi)); return r;
}
__device__ __forceinline__ void unpk2(u64 v, float& lo, float& hi) {
    asm("mov.b64 {%0, %1}, %2;" : "=f"(lo), "=f"(hi) : "l"(v));
}
__device__ __forceinline__ u64 f2mul(u64 a, u64 b) {
    u64 r; asm("mul.rn.f32x2 %0, %1, %2;" : "=l"(r) : "l"(a), "l"(b)); return r;
}
__device__ __forceinline__ u64 f2fma(u64 a, u64 b, u64 c) {
    u64 r; asm("fma.rn.f32x2 %0, %1, %2, %3;" : "=l"(r) : "l"(a), "l"(b), "l"(c)); return r;
}
__device__ __forceinline__ float2 cmulf(float2 a, float2 b) {
    return make_float2(a.x * b.x - a.y * b.y, a.x * b.y + a.y * b.x);
}
__device__ __forceinline__ u64 apply_phase(float2 w, u64 x) {
    float re, im; unpk2(x, re, im);
    return pk2(w.x * re - w.y * im, w.x * im + w.y * re);
}

// Real Givens butterfly: y0 = c*x0 - s*x1 ; y1 = s*x0 + c*x1  (4 f32x2 ops)
__device__ __forceinline__ void rbfly(u64 c, u64 s, u64 ns, u64& x0, u64& x1) {
    u64 y0 = f2fma(c, x0, f2mul(ns, x1));
    u64 y1 = f2fma(c, x1, f2mul(s, x0));
    x0 = y0; x1 = y1;
}

// Apply gate (layer, q) across register bit K; coefs from constant memory.
template<int K>
__device__ __forceinline__ void gate_q(int layer, int q, u64 a[16]) {
    u64 c = c_Rpk[layer][q][0], s = c_Rpk[layer][q][1], ns = c_Rpk[layer][q][2];
#pragma unroll
    for (int m = 0; m < 8; m++) {
        int j0 = ((m >> K) << (K + 1)) | (m & ((1 << K) - 1));
        rbfly(c, s, ns, a[j0], a[j0 | (1 << K)]);
    }
}

// Swizzles — bank-walked <=2-way for every phase pattern in each kernel
__device__ __forceinline__ int SWL2(int i) {
    return i ^ ((i >> 5) & 3) ^ ((i >> 2) & 4) ^ ((i >> 4) & 8);
}
__device__ __forceinline__ int SWH2(int i) {
    return i ^ ((i >> 5) & 3) ^ ((i >> 4) & 8);
}

// ---------------------------------------------------------------------------
// Prep stage 1 (1 block): fused U matrices + ZYZ decomposition per gate.
// ---------------------------------------------------------------------------
__global__ void prep_gates(const float* __restrict__ p) {
    int tid = threadIdx.x;
    if (tid >= NLAYERS * NQ) return;
    int l = tid / NQ, q = tid % NQ;
    float ty = p[l * 3 * NQ + q];
    float tz = p[l * 3 * NQ + NQ + q];
    float tx = p[l * 3 * NQ + 2 * NQ + q];
    float cy = cosf(0.5f * ty), sy = sinf(0.5f * ty);
    float cz = cosf(0.5f * tz), sz = sinf(0.5f * tz);
    float cx = cosf(0.5f * tx), sx = sinf(0.5f * tx);
    float2 em = make_float2(cz, -sz);
    float2 ep = make_float2(cz, sz);
    float2 u00 = make_float2(cx * cy * em.x + sx * sy * ep.y,
                             cx * cy * em.y - sx * sy * ep.x);
    float2 u01 = make_float2(-cx * sy * em.x + sx * cy * ep.y,
                             -cx * sy * em.y - sx * cy * ep.x);
    float2 u10 = make_float2(sx * cy * em.y + cx * sy * ep.x,
                             -sx * cy * em.x + cx * sy * ep.y);
    float2 u11 = make_float2(-sx * sy * em.y + cx * cy * ep.x,
                             sx * sy * em.x + cx * cy * ep.y);
    g_U[l][q][0] = u00; g_U[l][q][1] = u01;
    g_U[l][q][2] = u10; g_U[l][q][3] = u11;
    float c = sqrtf(u00.x * u00.x + u00.y * u00.y);
    float s = sqrtf(u01.x * u01.x + u01.y * u01.y);
    float p00 = atan2f(u00.y, u00.x);
    float p01 = atan2f(u01.y, u01.x);
    const float PI = 3.14159265358979f;
    float pA = 0.5f * (-p00 - p01 + PI);
    float pB = 0.5f * (-p00 + p01 - PI);
    g_pA[l][q] = pA; g_pB[l][q] = pB;
    g_Rpk[l][q][0] = pk2(c, c);
    g_Rpk[l][q][1] = pk2(s, s);
    g_Rpk[l][q][2] = pk2(-s, -s);
}

// ---------------------------------------------------------------------------
// Prep stage 2 (grid-parallel): product tables + combined diag tables.
// ---------------------------------------------------------------------------
__global__ void prep_tables() {
    int idx = blockIdx.x * blockDim.x + threadIdx.x;
    if (idx < 2048) {
        int i = idx;
        float2 ph = make_float2(1.f, 0.f);
        float2 pl = make_float2(1.f, 0.f);
        for (int q = 0; q <= 10; q++) {
            int b = (i >> (10 - q)) & 1;
            ph = cmulf(ph, g_U[0][q][b * 2]);
        }
        for (int q = 11; q <= 21; q++) {
            int b = (i >> (21 - q)) & 1;
            pl = cmulf(pl, g_U[0][q][b * 2]);
        }
        g_Phi[i] = ph;
        g_Plo[i] = pl;
    } else if (idx < 2048 + 7 * 2048) {
        int k0 = idx - 2048;
        int L = 1 + (k0 >> 11), x = k0 & 2047;
        float ang = 0.f;
        for (int k = 0; k < 11; k++) {
            int xb = (x >> k) & 1;
            ang += (xb ? 1.f : -1.f) * g_pB[L][10 - k];
            if (L >= 2) {
                int gb = xb ^ ((k < 10) ? ((x >> (k + 1)) & 1) : 0);
                ang += (gb ? 1.f : -1.f) * g_pA[L - 1][10 - k];
            }
        }
        float sv, cv; sincosf(ang, &sv, &cv);
        g_Whi[L][x] = make_float2(cv, sv);
    } else if (idx < 2048 + 7 * 2048 + 7 * 2 * 2048) {
        int k0 = idx - (2048 + 7 * 2048);
        int L = 1 + (k0 >> 12), carry = (k0 >> 11) & 1, x = k0 & 2047;
        float ang = 0.f;
        for (int b = 0; b < 11; b++) {
            int xb = (x >> b) & 1;
            ang += (xb ? 1.f : -1.f) * g_pB[L][21 - b];
            if (L >= 2) {
                int gb = xb ^ ((b < 10) ? ((x >> (b + 1)) & 1) : carry);
                ang += (gb ? 1.f : -1.f) * g_pA[L - 1][21 - b];
            }
        }
        float sv, cv; sincosf(ang, &sv, &cv);
        g_Wlo[L][carry][x] = make_float2(cv, sv);
    }
}

#define SMEM_BYTES (8192 * 8)

// ---------------------------------------------------------------------------
// L kernel: tile = 8192 contiguous amps (bits 0..12), 12 real rotations on
// bits 0..11 (qubits 10..21). blockIdx = global bits 13..21 (grid 512).
// Gray pairs stay aligned pairs -> LDG.128 state loads. Reg layout phase A:
// bit0 = local 0 (q21), bits1..3 = local 9,10,11 (q12,q11,q10).
// Phases: A{21,12,11,10}  B{20,19,18,13}  C{17,16,15,14}.
// ---------------------------------------------------------------------------
__global__ void __launch_bounds__(512, 2) kernelL(int layer, int srcIdx, int dstIdx, int first) {
    extern __shared__ u64 sh[];
    const int t = threadIdx.x;                 // 9 bits
    const unsigned h = blockIdx.x;             // global bits 13..21 (9 bits)
    const unsigned ghi = h ^ (h >> 1);
    const unsigned c12 = (h & 1u) << 12;
    u64 a[16];

    const int tm = t & 255, b12 = t >> 8;
    // ---- Phase A: i = (b12<<12)|(rr<<9)|(tm<<1)|v ; a idx = (rr<<1)|v
    if (first) {
#pragma unroll
        for (int r = 0; r < 16; r++) {
            unsigned i = (b12 << 12) | ((r >> 1) << 9) | (tm << 1) | (r & 1);
            unsigned glo = (i ^ (i >> 1)) ^ c12;
            float2 ph = g_Phi[(ghi << 2) | (glo >> 11)];
            float2 pl = g_Plo[glo & 2047];
            float2 v = cmulf(ph, pl);
            a[r] = pk2(v.x, v.y);
        }
    } else {
        const float2* __restrict__ src = g_state[srcIdx] + ((size_t)ghi << 13);
#pragma unroll
        for (int rr = 0; rr < 8; rr++) {
            unsigned i = (b12 << 12) | (rr << 9) | (tm << 1);
            unsigned glo = (i ^ (i >> 1)) ^ c12;
            unsigned base = glo & ~1u;
            ulonglong2 q = __ldg(reinterpret_cast<const ulonglong2*>(src + base));
            if (glo & 1) { a[(rr << 1)] = q.y; a[(rr << 1) | 1] = q.x; }
            else         { a[(rr << 1)] = q.x; a[(rr << 1) | 1] = q.y; }
        }
    }
    // Combined diag W at logical t = (h<<13)|i (pair-vectorized Wlo loads)
    {
        const float2 whi0 = __ldg(&g_Whi[layer][(h << 2) | (b12 << 1)]);
        const float2 whi1 = __ldg(&g_Whi[layer][(h << 2) | (b12 << 1) | 1]);
#pragma unroll
        for (int rr = 0; rr < 8; rr++) {
            int carry = rr >> 2;
            int ilo = ((rr & 3) << 9) | (tm << 1);
            float4 wv = __ldg(reinterpret_cast<const float4*>(&g_Wlo[layer][carry][ilo]));
            float2 whi = carry ? whi1 : whi0;
            a[(rr << 1)]     = apply_phase(cmulf(whi, make_float2(wv.x, wv.y)), a[(rr << 1)]);
            a[(rr << 1) | 1] = apply_phase(cmulf(whi, make_float2(wv.z, wv.w)), a[(rr << 1) | 1]);
        }
    }
    gate_q<0>(layer, 21, a);
    gate_q<1>(layer, 12, a);
    gate_q<2>(layer, 11, a);
    gate_q<3>(layer, 10, a);
#pragma unroll
    for (int r = 0; r < 16; r++) {
        unsigned i = (b12 << 12) | ((r >> 1) << 9) | (tm << 1) | (r & 1);
        sh[SWL2(i)] = a[r];
    }
    __syncthreads();

    // ---- Phase B: reg bits local {1,2,3,8} -> q20,q19,q18,q13
    // i = t0 | (rlow<<1) | (((t>>1)&15)<<4) | (r3<<8) | ((t>>5)<<9)
    const int u0 = t & 1, umid = (t >> 1) & 15, uhi = t >> 5;
#pragma unroll
    for (int r = 0; r < 16; r++) {
        int i = u0 | ((r & 7) << 1) | (umid << 4) | ((r >> 3) << 8) | (uhi << 9);
        a[r] = sh[SWL2(i)];
    }
    gate_q<0>(layer, 20, a);
    gate_q<1>(layer, 19, a);
    gate_q<2>(layer, 18, a);
    gate_q<3>(layer, 13, a);
#pragma unroll
    for (int r = 0; r < 16; r++) {
        int i = u0 | ((r & 7) << 1) | (umid << 4) | ((r >> 3) << 8) | (uhi << 9);
        sh[SWL2(i)] = a[r];
    }
    __syncthreads();

    // ---- Phase C: i = (hi5<<8)|(r<<4)|lo4 ; reg bits local 4..7 -> q17..q14
    const int hi5 = t >> 4, lo4 = t & 15;
#pragma unroll
    for (int r = 0; r < 16; r++) a[r] = sh[SWL2((hi5 << 8) | (r << 4) | lo4)];
    gate_q<0>(layer, 17, a);
    gate_q<1>(layer, 16, a);
    gate_q<2>(layer, 15, a);
    gate_q<3>(layer, 14, a);

    float2* __restrict__ dst = g_state[dstIdx] + ((size_t)h << 13);
#pragma unroll
    for (int r = 0; r < 16; r++) {
        float re, im; unpk2(a[r], re, im);
        dst[(hi5 << 8) | (r << 4) | lo4] = make_float2(re, im);
    }
}

// ---------------------------------------------------------------------------
// H kernel: tile bits {0..2} U {12..21} (8192 amps), 10 real rotations on
// global bits 12..21 (qubits 0..9). blockIdx = global bits 3..11 (grid 512).
// j(i) = ((i>>3)<<12)|(f<<3)|(i&7); local bit 0 in-thread -> LDG/STG.128.
// Phases: A{3,2,1}  B{7,6,5,4}  C{9,8,0}.
// ---------------------------------------------------------------------------
__global__ void __launch_bounds__(512, 2) kernelH(int layer, int srcIdx, int dstIdx,
                                                  float* __restrict__ probs) {
    extern __shared__ u64 sh[];
    const int t = threadIdx.x;                 // 9 bits
    const unsigned f = blockIdx.x;             // global bits 3..11 (9 bits)
    u64 a[16];

    // ---- Phase A: i = (s8<<12)|(rr<<9)|(shi<<3)|(s10<<1)|v ; a idx = (rr<<1)|v
    const int s8 = t >> 8, shi = (t >> 2) & 63, s10 = t & 3;
    {
        const float2* __restrict__ src = g_state[srcIdx];
        const unsigned jbase = ((((unsigned)s8 << 9) | shi) << 12) | (f << 3) | (s10 << 1);
#pragma unroll
        for (int rr = 0; rr < 8; rr++) {
            ulonglong2 q = __ldg(reinterpret_cast<const ulonglong2*>(src + (jbase | (rr << 18))));
            a[(rr << 1)] = q.x; a[(rr << 1) | 1] = q.y;
        }
    }
    gate_q<1>(layer, 3, a);    // local 9  -> qubit 3
    gate_q<2>(layer, 2, a);    // local 10 -> qubit 2
    gate_q<3>(layer, 1, a);    // local 11 -> qubit 1
#pragma unroll
    for (int r = 0; r < 16; r++) {
        int i = (s8 << 12) | ((r >> 1) << 9) | (shi << 3) | (s10 << 1) | (r & 1);
        sh[SWH2(i)] = a[r];
    }
    __syncthreads();

    // ---- Phase B: i = (hi4<<9)|(r<<5)|lo5 ; local 5..8 -> q7,q6,q5,q4
    const int hi4 = t >> 5, lo5 = t & 31;
#pragma unroll
    for (int r = 0; r < 16; r++) a[r] = sh[SWH2((hi4 << 9) | (r << 5) | lo5)];
    gate_q<0>(layer, 7, a);
    gate_q<1>(layer, 6, a);
    gate_q<2>(layer, 5, a);
    gate_q<3>(layer, 4, a);
#pragma unroll
    for (int r = 0; r < 16; r++) sh[SWH2((hi4 << 9) | (r << 5) | lo5)] = a[r];
    __syncthreads();

    // ---- Phase C: reg bits {0(v), 3(rB->q9), 4(rC->q8), 12(rD->q0)}
    // i = (rD<<12)|(wh<<5)|(rC<<4)|(rB<<3)|(wl<<1)|v ; a idx = (rD<<3)|(rC<<2)|(rB<<1)|v
    const int wl = t & 3, wh = (t >> 2) & 127;
#pragma unroll
    for (int r = 0; r < 16; r++) {
        int i = ((r >> 3) << 12) | (wh << 5) | (((r >> 2) & 1) << 4)
              | (((r >> 1) & 1) << 3) | (wl << 1) | (r & 1);
        a[r] = sh[SWH2(i)];
    }
    gate_q<1>(layer, 9, a);
    gate_q<2>(layer, 8, a);
    gate_q<3>(layer, 0, a);

    if (probs) {
        // layer 7: post-diag dropped (phase-invariant); fold final CNOT chain.
        // Pair (v=0/1) -> adjacent output slots {o&~1, o|1}.
#pragma unroll
        for (int rp = 0; rp < 8; rp++) {
            int i_even = ((rp >> 2) << 12) | (wh << 5) | (((rp >> 1) & 1) << 4)
                       | ((rp & 1) << 3) | (wl << 1);
            unsigned j = (((unsigned)i_even >> 3) << 12) | (f << 3) | (unsigned)(i_even & 7);
            unsigned o = j;
            o ^= o >> 1; o ^= o >> 2; o ^= o >> 4; o ^= o >> 8; o ^= o >> 16;
            float r0, i0, r1, i1;
            unpk2(a[(rp << 1)], r0, i0);
            unpk2(a[(rp << 1) | 1], r1, i1);
            float p0 = fmaf(r0, r0, i0 * i0);
            float p1 = fmaf(r1, r1, i1 * i1);
            unsigned po = o & 1;
            float2 pr = po ? make_float2(p1, p0) : make_float2(p0, p1);
            *reinterpret_cast<float2*>(&probs[o & ~1u]) = pr;
        }
    } else {
        float2* __restrict__ dst = g_state[dstIdx];
#pragma unroll
        for (int rp = 0; rp < 8; rp++) {
            int i_even = ((rp >> 2) << 12) | (wh << 5) | (((rp >> 1) & 1) << 4)
                       | ((rp & 1) << 3) | (wl << 1);
            unsigned j = (((unsigned)i_even >> 3) << 12) | (f << 3) | (unsigned)(i_even & 7);
            ulonglong2 q;
            q.x = a[(rp << 1)]; q.y = a[(rp << 1) | 1];
            *reinterpret_cast<ulonglong2*>(dst + j) = q;
        }
    }
}

// ---------------------------------------------------------------------------
extern "C" void kernel_launch(void* const* d_in, const int* in_sizes, int n_in,
                              void* d_out, int out_size) {
    (void)in_sizes; (void)n_in; (void)out_size;
    const float* params = (const float*)d_in[0];
    float* out = (float*)d_out;

    cudaFuncSetAttribute(kernelL, cudaFuncAttributeMaxDynamicSharedMemorySize, SMEM_BYTES);
    cudaFuncSetAttribute(kernelH, cudaFuncAttributeMaxDynamicSharedMemorySize, SMEM_BYTES);

    prep_gates<<<1, 192>>>(params);
    // Broadcast gate coefficients into constant memory (D2D copy, graph-legal)
    void* cdst = nullptr; void* csrc = nullptr;
    cudaGetSymbolAddress(&cdst, c_Rpk);
    cudaGetSymbolAddress(&csrc, g_Rpk);
    cudaMemcpyAsync(cdst, csrc, NLAYERS * NQ * 3 * sizeof(u64),
                    cudaMemcpyDeviceToDevice);
    prep_tables<<<88, 512>>>();

    // Layer 0 folded into tables; layer-(l-1) CNOT chain folded into L's gray
    // load; layer-7 chain folded into the prob scatter; both diagonals of each
    // layer boundary folded into ONE combined phase multiply at L-load.
    kernelL<<<512, 512, SMEM_BYTES>>>(1, /*src*/1, /*dst*/0, /*first*/1);
    kernelH<<<512, 512, SMEM_BYTES>>>(1, 0, 1, nullptr);
    for (int ll = 2; ll <= 7; ll++) {
        kernelL<<<512, 512, SMEM_BYTES>>>(ll, 1, 0, 0);
        kernelH<<<512, 512, SMEM_BYTES>>>(ll, 0, 1, (ll == 7) ? out : nullptr);
    }
}